// round 1
// baseline (speedup 1.0000x reference)
#include <cuda_runtime.h>
#include <cstddef>

// Problem constants
#define B_ 2
#define L_ 1024
#define D_ 128
#define V_ 5

// Scratch tables (allocation-free rule: __device__ globals)
__device__ float g_A[V_][D_];    // P1[v][e] + b[e]
__device__ float g_P2[V_][D_];   // P2[v][e]

// ---------------------------------------------------------------------------
// Kernel 1: build the 5x128 tables.
//   P1[v][e] = sum_d emb[v][d] * W[e*2D + d]
//   P2[v][e] = sum_d emb[v][d] * W[e*2D + D + d]
// ---------------------------------------------------------------------------
__global__ void tables_kernel(const float* __restrict__ emb,
                              const float* __restrict__ W,
                              const float* __restrict__ bias) {
    int e = threadIdx.x;  // 0..127
    const float* w1 = W + (size_t)e * (2 * D_);
    const float* w2 = w1 + D_;
    float be = bias[e];
    #pragma unroll
    for (int v = 0; v < V_; v++) {
        const float* ev = emb + v * D_;
        float s1 = 0.f, s2 = 0.f;
        #pragma unroll 4
        for (int d = 0; d < D_; d++) {
            float x = ev[d];
            s1 += x * w1[d];
            s2 += x * w2[d];
        }
        g_A[v][e]  = s1 + be;
        g_P2[v][e] = s2;
    }
}

// ---------------------------------------------------------------------------
// Kernel 2: s output = emb gather.  One float4 per thread-iteration.
//   s[b][l][d] = emb[x[b][l]][d]
// total float4s: 2*1024*32 = 65536
// ---------------------------------------------------------------------------
__global__ void s_kernel(const int* __restrict__ x,
                         const float* __restrict__ emb,
                         float4* __restrict__ out_s) {
    int idx = blockIdx.x * blockDim.x + threadIdx.x;
    if (idx >= B_ * L_ * (D_ / 4)) return;
    int row = idx >> 5;        // (b*L + l)
    int d4  = idx & 31;
    int v = x[row];
    out_s[idx] = reinterpret_cast<const float4*>(emb)[v * (D_ / 4) + d4];
}

// ---------------------------------------------------------------------------
// Kernel 3: the 1 GiB m output.
//   m[b][e][l1][l2] = A[x[b][l1]][e] + P2[x[b][l2]][e]
// grid = B*D*8 = 2048 blocks; each block writes 128 rows x 1024 cols (512 KiB)
// ---------------------------------------------------------------------------
__global__ __launch_bounds__(256, 8)
void m_kernel(const int* __restrict__ x, float4* __restrict__ out_m) {
    int slab  = blockIdx.x >> 3;   // 0..255  -> (b,e)
    int chunk = blockIdx.x & 7;    // l1 chunk of 128 rows
    int b = slab >> 7;
    int e = slab & 127;

    __shared__ float4 pv2[L_ / 4];   // 1024 floats, P2[x[b][l2]][e]
    __shared__ float  pc1[128];      // A[x[b][l1]][e] for this chunk
    __shared__ float  a5[V_], p5[V_];

    if (threadIdx.x < V_) {
        a5[threadIdx.x] = g_A[threadIdx.x][e];
        p5[threadIdx.x] = g_P2[threadIdx.x][e];
    }
    __syncthreads();

    const int* xb = x + b * L_;
    float* pv2f = reinterpret_cast<float*>(pv2);
    for (int l2 = threadIdx.x; l2 < L_; l2 += blockDim.x)
        pv2f[l2] = p5[xb[l2]];

    int l1base = chunk * 128;
    if (threadIdx.x < 128)
        pc1[threadIdx.x] = a5[xb[l1base + threadIdx.x]];
    __syncthreads();

    // 128 rows x 256 float4 = 32768 float4 per block
    float4* out = out_m + ((size_t)slab * L_ + l1base) * (L_ / 4);
    #pragma unroll 4
    for (int idx = threadIdx.x; idx < 128 * (L_ / 4); idx += 256) {
        int r = idx >> 8;      // row within chunk (warp-uniform)
        int q = idx & 255;     // float4 column
        float  c = pc1[r];
        float4 v = pv2[q];
        v.x += c; v.y += c; v.z += c; v.w += c;
        out[idx] = v;
    }
}

// ---------------------------------------------------------------------------
// kernel_launch
// inputs (metadata order): x(int32, B*L), emb_table(f32, V*D),
//                          W(f32, D*2D), b(f32, D)
// output: concat(s, m) as f32: s = B*L*D, m = B*D*L*L
// ---------------------------------------------------------------------------
extern "C" void kernel_launch(void* const* d_in, const int* in_sizes, int n_in,
                              void* d_out, int out_size) {
    const int*   x   = (const int*)d_in[0];
    const float* emb = (const float*)d_in[1];
    const float* W   = (const float*)d_in[2];
    const float* bias= (const float*)d_in[3];

    float* out_s = (float*)d_out;
    float* out_m = out_s + (size_t)B_ * L_ * D_;

    tables_kernel<<<1, 128>>>(emb, W, bias);

    int s_f4 = B_ * L_ * (D_ / 4);               // 65536
    s_kernel<<<(s_f4 + 255) / 256, 256>>>(x, emb, (float4*)out_s);

    m_kernel<<<B_ * D_ * 8, 256>>>(x, (float4*)out_m);
}

// round 2
// speedup vs baseline: 1.6179x; 1.6179x over previous
#include <cuda_runtime.h>
#include <cstddef>

// Problem constants
#define B_ 2
#define L_ 1024
#define D_ 128
#define V_ 5

// ---------------------------------------------------------------------------
// Kernel: s output = emb gather (1 MiB), one float4 per thread.
//   s[b][l][d] = emb[x[b][l]][d]
// ---------------------------------------------------------------------------
__global__ void s_kernel(const int* __restrict__ x,
                         const float* __restrict__ emb,
                         float4* __restrict__ out_s) {
    int idx = blockIdx.x * blockDim.x + threadIdx.x;
    if (idx >= B_ * L_ * (D_ / 4)) return;
    int row = idx >> 5;        // (b*L + l)
    int d4  = idx & 31;
    int v = x[row];
    out_s[idx] = reinterpret_cast<const float4*>(emb)[v * (D_ / 4) + d4];
}

// ---------------------------------------------------------------------------
// Kernel: the 1 GiB m output, with the 5x128 projection tables fused into the
// block prologue (kills the former 102us serialized tables_kernel).
//
//   A[v][e]  = dot(emb[v], W[e][0:128]) + bias[e]
//   P2[v][e] = dot(emb[v], W[e][128:256])
//   m[b][e][l1][l2] = A[x[b][l1]][e] + P2[x[b][l2]][e]
//
// grid = B*D*8 = 2048 blocks; each block handles one (b,e) and a 128-row l1
// chunk: writes 128 x 1024 floats = 512 KiB contiguous.
// ---------------------------------------------------------------------------
__global__ __launch_bounds__(256, 8)
void m_kernel(const int* __restrict__ x,
              const float* __restrict__ emb,
              const float* __restrict__ W,
              const float* __restrict__ bias,
              float4* __restrict__ out_m) {
    int slab  = blockIdx.x >> 3;   // 0..255  -> (b,e)
    int chunk = blockIdx.x & 7;    // l1 chunk of 128 rows
    int b = slab >> 7;
    int e = slab & 127;

    __shared__ float4 pv2[L_ / 4];   // 1024 floats: P2[x[b][l2]][e]
    __shared__ float  pc1[128];      // A[x[b][l1]][e] for this chunk
    __shared__ int    sx[L_];        // x[b][:]
    __shared__ float  a5[V_], p5[V_];

    int tid  = threadIdx.x;
    int wid  = tid >> 5;
    int lane = tid & 31;

    // Stage x[b][:] (4 KiB) with all threads.
    const int* xb = x + b * L_;
    #pragma unroll
    for (int i = tid; i < L_; i += 256) sx[i] = xb[i];

    // Warps 0..4: per-block table build. Warp v computes both dot products
    // for vocab entry v against W row e (lane-strided, coalesced, L2-hot).
    if (wid < V_) {
        const float* w1 = W + (size_t)e * (2 * D_);
        const float* ev = emb + wid * D_;
        float s1 = 0.f, s2 = 0.f;
        #pragma unroll
        for (int d = lane; d < D_; d += 32) {
            float xv = ev[d];
            s1 += xv * w1[d];
            s2 += xv * w1[D_ + d];
        }
        #pragma unroll
        for (int o = 16; o; o >>= 1) {
            s1 += __shfl_xor_sync(0xFFFFFFFFu, s1, o);
            s2 += __shfl_xor_sync(0xFFFFFFFFu, s2, o);
        }
        if (lane == 0) {
            a5[wid] = s1 + bias[e];
            p5[wid] = s2;
        }
    }
    __syncthreads();

    // Build row/col vectors from the tiny tables.
    int l1base = chunk * 128;
    float* pv2f = reinterpret_cast<float*>(pv2);
    #pragma unroll
    for (int l2 = tid; l2 < L_; l2 += 256) pv2f[l2] = p5[sx[l2]];
    if (tid < 128) pc1[tid] = a5[sx[l1base + tid]];
    __syncthreads();

    // Streaming store: 128 rows x 256 float4 = 32768 float4 per block.
    float4* out = out_m + ((size_t)slab * L_ + l1base) * (L_ / 4);
    #pragma unroll 4
    for (int idx = tid; idx < 128 * (L_ / 4); idx += 256) {
        int r = idx >> 8;      // row within chunk (warp-uniform)
        int q = idx & 255;     // float4 column
        float  c = pc1[r];
        float4 v = pv2[q];
        v.x += c; v.y += c; v.z += c; v.w += c;
        out[idx] = v;
    }
}

// ---------------------------------------------------------------------------
// kernel_launch
// inputs (metadata order): x(int32, B*L), emb_table(f32, V*D),
//                          W(f32, D*2D), b(f32, D)
// output: concat(s, m) as f32: s = B*L*D, m = B*D*L*L
// ---------------------------------------------------------------------------
extern "C" void kernel_launch(void* const* d_in, const int* in_sizes, int n_in,
                              void* d_out, int out_size) {
    const int*   x    = (const int*)d_in[0];
    const float* emb  = (const float*)d_in[1];
    const float* W    = (const float*)d_in[2];
    const float* bias = (const float*)d_in[3];

    float* out_s = (float*)d_out;
    float* out_m = out_s + (size_t)B_ * L_ * D_;

    int s_f4 = B_ * L_ * (D_ / 4);               // 65536
    s_kernel<<<(s_f4 + 255) / 256, 256>>>(x, emb, (float4*)out_s);

    m_kernel<<<B_ * D_ * 8, 256>>>(x, emb, W, bias, (float4*)out_m);
}

// round 3
// speedup vs baseline: 1.6862x; 1.0422x over previous
#include <cuda_runtime.h>
#include <cstddef>

// Problem constants
#define B_ 2
#define L_ 1024
#define D_ 128
#define V_ 5

// ---------------------------------------------------------------------------
// Single fused kernel.
//   Tables (per block, tiny):
//     A[v][e]  = dot(emb[v], W[e][0:128]) + bias[e]
//     P2[v][e] = dot(emb[v], W[e][128:256])
//   m[b][e][l1][l2] = A[x[b][l1]][e] + P2[x[b][l2]][e]     (1 GiB stream)
//   s[b][l][d]      = emb[x[b][l]][d]                      (1 MiB, fused slice)
//
// grid = B*D*8 = 2048 blocks; each handles one (b,e) and a 128-row l1 chunk
// (512 KiB contiguous store), plus a 32-float4 slice of s.
// ---------------------------------------------------------------------------
__global__ __launch_bounds__(256, 8)
void fused_kernel(const int* __restrict__ x,
                  const float* __restrict__ emb,
                  const float* __restrict__ W,
                  const float* __restrict__ bias,
                  float4* __restrict__ out_s,
                  float4* __restrict__ out_m) {
    int slab  = blockIdx.x >> 3;   // 0..255  -> (b,e)
    int chunk = blockIdx.x & 7;    // l1 chunk of 128 rows
    int b = slab >> 7;
    int e = slab & 127;

    __shared__ float4 pv2[L_ / 4];   // 1024 floats: P2[x[b][l2]][e]
    __shared__ float  pc1[128];      // A[x[b][l1]][e] for this chunk
    __shared__ int    sx[L_];        // x[b][:]
    __shared__ float  a5[V_], p5[V_];

    int tid  = threadIdx.x;
    int wid  = tid >> 5;
    int lane = tid & 31;

    // Stage x[b][:] (4 KiB).
    const int* xb = x + b * L_;
    #pragma unroll
    for (int i = tid; i < L_; i += 256) sx[i] = xb[i];

    // Warps 0..4: table build. Warp v computes both dot products for vocab
    // entry v against W row e (lane-strided, coalesced, L2-hot).
    if (wid < V_) {
        const float* w1 = W + (size_t)e * (2 * D_);
        const float* ev = emb + wid * D_;
        float s1 = 0.f, s2 = 0.f;
        #pragma unroll
        for (int d = lane; d < D_; d += 32) {
            float xv = ev[d];
            s1 += xv * w1[d];
            s2 += xv * w1[D_ + d];
        }
        #pragma unroll
        for (int o = 16; o; o >>= 1) {
            s1 += __shfl_xor_sync(0xFFFFFFFFu, s1, o);
            s2 += __shfl_xor_sync(0xFFFFFFFFu, s2, o);
        }
        if (lane == 0) {
            a5[wid] = s1 + bias[e];
            p5[wid] = s2;
        }
    }
    __syncthreads();

    // Build row/col vectors from the tiny tables.
    int l1base = chunk * 128;
    float* pv2f = reinterpret_cast<float*>(pv2);
    #pragma unroll
    for (int l2 = tid; l2 < L_; l2 += 256) pv2f[l2] = p5[sx[l2]];
    if (tid < 128) pc1[tid] = a5[sx[l1base + tid]];
    __syncthreads();

    // Main streaming store: 128 rows x 256 float4 = 32768 float4 per block.
    float4* out = out_m + ((size_t)slab * L_ + l1base) * (L_ / 4);
    #pragma unroll 4
    for (int idx = tid; idx < 128 * (L_ / 4); idx += 256) {
        int r = idx >> 8;      // row within chunk (warp-uniform)
        int q = idx & 255;     // float4 column
        float  c = pc1[r];
        float4 v = pv2[q];
        v.x += c; v.y += c; v.z += c; v.w += c;
        __stcs(&out[idx], v);  // streaming: don't retain in L2
    }

    // Fused s slice: 65536 float4 total / 2048 blocks = 32 per block
    // (warp 0 only; emb rows are L2-resident).
    if (wid == 0) {
        int idx = blockIdx.x * 32 + lane;            // < 65536
        int row = idx >> 5;                          // (b*L + l), global
        int d4  = idx & 31;
        int v = x[row];
        out_s[idx] = reinterpret_cast<const float4*>(emb)[v * (D_ / 4) + d4];
    }
}

// ---------------------------------------------------------------------------
// kernel_launch
// inputs (metadata order): x(int32, B*L), emb_table(f32, V*D),
//                          W(f32, D*2D), b(f32, D)
// output: concat(s, m) as f32: s = B*L*D, m = B*D*L*L
// ---------------------------------------------------------------------------
extern "C" void kernel_launch(void* const* d_in, const int* in_sizes, int n_in,
                              void* d_out, int out_size) {
    const int*   x    = (const int*)d_in[0];
    const float* emb  = (const float*)d_in[1];
    const float* W    = (const float*)d_in[2];
    const float* bias = (const float*)d_in[3];

    float* out_s = (float*)d_out;
    float* out_m = out_s + (size_t)B_ * L_ * D_;

    fused_kernel<<<B_ * D_ * 8, 256>>>(x, emb, W, bias,
                                       (float4*)out_s, (float4*)out_m);
}